// round 13
// baseline (speedup 1.0000x reference)
#include <cuda_runtime.h>
#include <cuda_fp16.h>
#include <math.h>
#include <stdint.h>

// Problem constants (B=8, S=2048, D=2048, H=2048, E=4, TOP_K=2)
#define NTOK 16384
#define DDIM 2048
#define HDIM 2048
#define NEXP 4
#define NCH  32              // K/64 chunks

// Tile config: 128M x 256N CTA, 256 threads (8 warps: 2M x 4N, 64x64 warp tile)
#define BM 128
#define BN 256
#define BK 64
#define NTHREADS 256
#define TILE_A 16384                        // 128 rows x 128B (64 fp16)
#define TILE_B 32768                        // 256 rows x 128B
#define STAGE_BYTES (TILE_A + TILE_B)       // A | B = 49152
#define NSTG 3
#define SMEM_TOTAL (1024 + NSTG * STAGE_BYTES) // 148480

// ---------------------------------------------------------------------------
// Scratch (static device arrays — no runtime allocation)
// ---------------------------------------------------------------------------
__device__ int   g_cnt[NEXP];
__device__ int   g_tok[NEXP][NTOK];
__device__ float g_wgt[NEXP][NTOK];
__device__ int   g_rank[NEXP][NTOK];

__device__ __align__(16) __half g_xf[(size_t)NTOK * DDIM];          // x fp16
__device__ __align__(16) __half g_w1f[(size_t)NEXP * HDIM * DDIM];  // [e][n][k]
__device__ __align__(16) __half g_w2f[(size_t)NEXP * HDIM * HDIM];
__device__ __align__(16) __half g_h1f[(size_t)NEXP * NTOK * HDIM];  // gelu out fp16
__device__ __align__(16) float  g_outr[2][(size_t)NTOK * HDIM];     // rank-split

// ---------------------------------------------------------------------------
// Helpers
// ---------------------------------------------------------------------------
__device__ __forceinline__ uint32_t smem_u32(const void* p) {
    uint32_t a;
    asm("{ .reg .u64 t; cvta.to.shared.u64 t, %1; cvt.u32.u64 %0, t; }"
        : "=r"(a) : "l"(p));
    return a;
}
// 128B-row XOR swizzle
__device__ __forceinline__ uint32_t swz(uint32_t row, uint32_t byteoff) {
    uint32_t c16 = byteoff >> 4, lo = byteoff & 15;
    return row * 128 + (((c16 ^ (row & 7)) & 7) << 4) + lo;
}
__device__ __forceinline__ void cp16(uint32_t saddr, const void* gaddr) {
    asm volatile("cp.async.cg.shared.global [%0], [%1], 16;" :: "r"(saddr), "l"(gaddr));
}
#define CP_COMMIT() asm volatile("cp.async.commit_group;" ::: "memory")
#define CP_WAIT0()  asm volatile("cp.async.wait_group 0;" ::: "memory")
#define CP_WAIT1()  asm volatile("cp.async.wait_group 1;" ::: "memory")

__device__ __forceinline__ void ldsm_x4(uint32_t* r, uint32_t addr) {
    asm volatile("ldmatrix.sync.aligned.m8n8.x4.shared.b16 {%0,%1,%2,%3}, [%4];"
        : "=r"(r[0]), "=r"(r[1]), "=r"(r[2]), "=r"(r[3]) : "r"(addr));
}
__device__ __forceinline__ void mma_f16(float* d, const uint32_t* a, const uint32_t* b) {
    asm volatile(
        "mma.sync.aligned.m16n8k16.row.col.f32.f16.f16.f32 "
        "{%0,%1,%2,%3}, {%4,%5,%6,%7}, {%8,%9}, {%0,%1,%2,%3};"
        : "+f"(d[0]), "+f"(d[1]), "+f"(d[2]), "+f"(d[3])
        : "r"(a[0]), "r"(a[1]), "r"(a[2]), "r"(a[3]), "r"(b[0]), "r"(b[1]));
}

// ---------------------------------------------------------------------------
__global__ void reset_kernel() {
    if (threadIdx.x < NEXP) g_cnt[threadIdx.x] = 0;
}

// Fused: x fp32 -> fp16 plane AND router (top-2 + renorm + per-expert lists).
__global__ void prep_x(const float* __restrict__ x, const float* __restrict__ gw) {
    int tok = blockIdx.x * 8 + (threadIdx.x >> 5);
    int lane = threadIdx.x & 31;
    const float4* src = (const float4*)(x + (size_t)tok * DDIM);
    const float4* g4 = (const float4*)gw;
    uint2* xf = (uint2*)(g_xf + (size_t)tok * DDIM);

    float a0 = 0.f, a1 = 0.f, a2 = 0.f, a3 = 0.f;
#pragma unroll
    for (int j = 0; j < 16; j++) {
        int k4 = lane + j * 32;
        float4 v = src[k4];
        float4 w0 = g4[k4], w1 = g4[512 + k4], w2 = g4[1024 + k4], w3 = g4[1536 + k4];
        a0 = fmaf(v.x, w0.x, fmaf(v.y, w0.y, fmaf(v.z, w0.z, fmaf(v.w, w0.w, a0))));
        a1 = fmaf(v.x, w1.x, fmaf(v.y, w1.y, fmaf(v.z, w1.z, fmaf(v.w, w1.w, a1))));
        a2 = fmaf(v.x, w2.x, fmaf(v.y, w2.y, fmaf(v.z, w2.z, fmaf(v.w, w2.w, a2))));
        a3 = fmaf(v.x, w3.x, fmaf(v.y, w3.y, fmaf(v.z, w3.z, fmaf(v.w, w3.w, a3))));
        __half2 p0 = __floats2half2_rn(v.x, v.y);
        __half2 p1 = __floats2half2_rn(v.z, v.w);
        xf[k4] = make_uint2(*(uint32_t*)&p0, *(uint32_t*)&p1);
    }
#pragma unroll
    for (int o = 16; o; o >>= 1) {
        a0 += __shfl_xor_sync(0xffffffffu, a0, o);
        a1 += __shfl_xor_sync(0xffffffffu, a1, o);
        a2 += __shfl_xor_sync(0xffffffffu, a2, o);
        a3 += __shfl_xor_sync(0xffffffffu, a3, o);
    }
    if (lane == 0) {
        float l[4] = {a0, a1, a2, a3};
        int i0 = 0;
#pragma unroll
        for (int e = 1; e < 4; e++) if (l[e] > l[i0]) i0 = e;
        int i1 = (i0 == 0) ? 1 : 0;
#pragma unroll
        for (int e = 0; e < 4; e++) if (e != i0 && l[e] > l[i1]) i1 = e;
        float w0 = 1.0f / (1.0f + expf(l[i1] - l[i0]));
        float w1 = 1.0f - w0;
        int s0 = atomicAdd(&g_cnt[i0], 1);
        g_tok[i0][s0] = tok; g_wgt[i0][s0] = w0; g_rank[i0][s0] = 0;
        int s1 = atomicAdd(&g_cnt[i1], 1);
        g_tok[i1][s1] = tok; g_wgt[i1][s1] = w1; g_rank[i1][s1] = 1;
    }
}

// w [E][K][N] fp32 -> wt [E][N][K] fp16; z covers both weights (0-3: w1, 4-7: w2)
__global__ void transpose_w(const float* __restrict__ w1, const float* __restrict__ w2) {
    __shared__ float tile[32][33];
    int which = blockIdx.z >> 2;
    int e = blockIdx.z & 3;
    int n0 = blockIdx.x * 32, k0 = blockIdx.y * 32;
    const float* src = (which ? w2 : w1) + (size_t)e * DDIM * HDIM;
    int tx = threadIdx.x, ty = threadIdx.y;
#pragma unroll
    for (int i = 0; i < 4; i++) {
        int k = k0 + ty + i * 8;
        tile[ty + i * 8][tx] = src[(size_t)k * HDIM + n0 + tx];
    }
    __syncthreads();
    __half* of = which ? g_w2f : g_w1f;
#pragma unroll
    for (int i = 0; i < 4; i++) {
        int n = n0 + ty + i * 8;
        float v = tile[tx][ty + i * 8];
        size_t o = ((size_t)e * HDIM + n) * DDIM + k0 + tx;
        of[o] = __float2half_rn(v);
    }
}

// ---------------------------------------------------------------------------
// GEMM core: fp16, m16n8k16, ldmatrix, 64x64 warp tile (4 mt x 8 nt).
// Fragments double-buffered: s+1 ldsm batch issued before the 32 MMAs of s.
// 8 warps: wm = wid & 1 (2 x 64 rows), wn = wid >> 1 (4 x 64 cols).
// ---------------------------------------------------------------------------
__device__ __forceinline__ void compute_chunk(uint32_t base, int wm, int wn,
                                              int lane, float acc[4][8][4]) {
    uint32_t aF = base;
    uint32_t bF = base + TILE_A;

    uint32_t a_row  = (uint32_t)(wm * 64) + (lane & 15);
    uint32_t a_kb   = (uint32_t)((lane >> 4) << 4);
    uint32_t b_row0 = (uint32_t)(wn * 64) + (((lane >> 4) & 1) << 3) + (lane & 7);
    uint32_t b_kb   = (uint32_t)(((lane >> 3) & 1) << 4);

    uint32_t af[2][4][4], rb[2][4][4];
    // preload s = 0 fragments
#pragma unroll
    for (int mt = 0; mt < 4; mt++)
        ldsm_x4(af[0][mt], aF + swz(a_row + mt * 16, a_kb));
#pragma unroll
    for (int p = 0; p < 4; p++)
        ldsm_x4(rb[0][p], bF + swz(b_row0 + p * 16, b_kb));

#pragma unroll
    for (int s = 0; s < 4; s++) {
        int cur = s & 1, nxt = cur ^ 1;
        if (s < 3) {
            uint32_t boff = (uint32_t)(s + 1) * 32;
#pragma unroll
            for (int mt = 0; mt < 4; mt++)
                ldsm_x4(af[nxt][mt], aF + swz(a_row + mt * 16, boff + a_kb));
#pragma unroll
            for (int p = 0; p < 4; p++)
                ldsm_x4(rb[nxt][p], bF + swz(b_row0 + p * 16, boff + b_kb));
        }
#pragma unroll
        for (int p = 0; p < 4; p++) {
#pragma unroll
            for (int mt = 0; mt < 4; mt++) {
                mma_f16(acc[mt][2 * p],     af[cur][mt], rb[cur][p]);
                mma_f16(acc[mt][2 * p + 1], af[cur][mt], rb[cur][p] + 2);
            }
        }
    }
}

// ---------------------------------------------------------------------------
// GEMM1: h1[e][m][:] = gelu(x[tok] @ w1[e] + b1[e]) -> fp16
// ---------------------------------------------------------------------------
__global__ void __launch_bounds__(NTHREADS, 1)
moe_gemm1(const float* __restrict__ b1) {
    int e = blockIdx.z;
    int cnt = g_cnt[e];
    int m0 = blockIdx.y * BM;
    if (m0 >= cnt) return;
    int n0 = blockIdx.x * BN;

    __shared__ int s_tok[BM];
    extern __shared__ char dynsm[];
    uint32_t ab = (smem_u32(dynsm) + 1023) & ~1023u;

    int tid = threadIdx.x;
    int wid = tid >> 5, lane = tid & 31;
    int wm = wid & 1, wn = wid >> 1;

    if (tid < BM) {
        int s = m0 + tid; if (s > cnt - 1) s = cnt - 1;
        s_tok[tid] = g_tok[e][s];
    }
    __syncthreads();

    const __half* wf = g_w1f + (size_t)e * HDIM * DDIM;

    float acc[4][8][4];
#pragma unroll
    for (int i = 0; i < 4; i++)
#pragma unroll
        for (int j = 0; j < 8; j++)
#pragma unroll
            for (int k = 0; k < 4; k++) acc[i][j][k] = 0.f;

    int r = tid >> 3, c16 = tid & 7;           // 256 threads: 32 rows x 8 chunks
    auto load_chunk = [&](int c, uint32_t bufb) {
        int k0 = c * BK;
#pragma unroll
        for (int i = 0; i < 4; i++) {           // A: 128 rows
            int rr = r + i * 32;
            uint32_t so = swz((uint32_t)rr, (uint32_t)(c16 * 16));
            cp16(ab + bufb + so, g_xf + (size_t)s_tok[rr] * DDIM + k0 + c16 * 8);
        }
#pragma unroll
        for (int i = 0; i < 8; i++) {           // B: 256 rows
            int rr = r + i * 32;
            uint32_t so = swz((uint32_t)rr, (uint32_t)(c16 * 16));
            cp16(ab + bufb + TILE_A + so, wf + (size_t)(n0 + rr) * DDIM + k0 + c16 * 8);
        }
        CP_COMMIT();
    };

    load_chunk(0, 0);
    load_chunk(1, STAGE_BYTES);
    for (int c = 0; c < NCH; c++) {
        if (c + 1 < NCH) CP_WAIT1(); else CP_WAIT0();
        __syncthreads();
        if (c + 2 < NCH) load_chunk(c + 2, (uint32_t)((c + 2) % NSTG) * STAGE_BYTES);
        compute_chunk(ab + (uint32_t)(c % NSTG) * STAGE_BYTES, wm, wn, lane, acc);
    }

    // Epilogue: bias + exact GELU -> fp16
    int g = lane >> 2, tig = lane & 3;
    __half* h1f = g_h1f + (size_t)e * NTOK * HDIM;
    const float* bias = b1 + (size_t)e * HDIM;
#pragma unroll
    for (int nt = 0; nt < 8; nt++) {
        int n = n0 + wn * 64 + nt * 8 + tig * 2;
        float bv0 = bias[n], bv1 = bias[n + 1];
#pragma unroll
        for (int mt = 0; mt < 4; mt++) {
#pragma unroll
            for (int half = 0; half < 2; half++) {
                int m = m0 + wm * 64 + mt * 16 + g + half * 8;
                if (m < cnt) {
                    float v0 = acc[mt][nt][half * 2 + 0] + bv0;
                    float v1 = acc[mt][nt][half * 2 + 1] + bv1;
                    float g0 = 0.5f * v0 * (1.0f + erff(v0 * 0.70710678118654752f));
                    float g1 = 0.5f * v1 * (1.0f + erff(v1 * 0.70710678118654752f));
                    __half2 hv = __floats2half2_rn(g0, g1);
                    *(uint32_t*)(h1f + (size_t)m * HDIM + n) = *(uint32_t*)&hv;
                }
            }
        }
    }
}

// ---------------------------------------------------------------------------
// GEMM2: g_outr[rank][tok][:] = wgt * (h1[e] @ w2[e] + b2[e])
// ---------------------------------------------------------------------------
__global__ void __launch_bounds__(NTHREADS, 1)
moe_gemm2(const float* __restrict__ b2) {
    int e = blockIdx.z;
    int cnt = g_cnt[e];
    int m0 = blockIdx.y * BM;
    if (m0 >= cnt) return;
    int n0 = blockIdx.x * BN;

    __shared__ int   s_tok[BM];
    __shared__ float s_wgt[BM];
    __shared__ int   s_rnk[BM];
    extern __shared__ char dynsm[];
    uint32_t ab = (smem_u32(dynsm) + 1023) & ~1023u;

    int tid = threadIdx.x;
    int wid = tid >> 5, lane = tid & 31;
    int wm = wid & 1, wn = wid >> 1;

    if (tid < BM) {
        int s = m0 + tid; if (s > cnt - 1) s = cnt - 1;
        s_tok[tid] = g_tok[e][s];
        s_wgt[tid] = g_wgt[e][s];
        s_rnk[tid] = g_rank[e][s];
    }
    __syncthreads();

    const __half* ahp = g_h1f + (size_t)e * NTOK * HDIM;
    const __half* wf = g_w2f + (size_t)e * HDIM * HDIM;

    float acc[4][8][4];
#pragma unroll
    for (int i = 0; i < 4; i++)
#pragma unroll
        for (int j = 0; j < 8; j++)
#pragma unroll
            for (int k = 0; k < 4; k++) acc[i][j][k] = 0.f;

    int r = tid >> 3, c16 = tid & 7;
    auto load_chunk = [&](int c, uint32_t bufb) {
        int k0 = c * BK;
#pragma unroll
        for (int i = 0; i < 4; i++) {
            int rr = r + i * 32;
            uint32_t so = swz((uint32_t)rr, (uint32_t)(c16 * 16));
            int mm = m0 + rr; if (mm > cnt - 1) mm = cnt - 1;
            cp16(ab + bufb + so, ahp + (size_t)mm * HDIM + k0 + c16 * 8);
        }
#pragma unroll
        for (int i = 0; i < 8; i++) {
            int rr = r + i * 32;
            uint32_t so = swz((uint32_t)rr, (uint32_t)(c16 * 16));
            cp16(ab + bufb + TILE_A + so, wf + (size_t)(n0 + rr) * HDIM + k0 + c16 * 8);
        }
        CP_COMMIT();
    };

    load_chunk(0, 0);
    load_chunk(1, STAGE_BYTES);
    for (int c = 0; c < NCH; c++) {
        if (c + 1 < NCH) CP_WAIT1(); else CP_WAIT0();
        __syncthreads();
        if (c + 2 < NCH) load_chunk(c + 2, (uint32_t)((c + 2) % NSTG) * STAGE_BYTES);
        compute_chunk(ab + (uint32_t)(c % NSTG) * STAGE_BYTES, wm, wn, lane, acc);
    }

    // Epilogue: (acc + b2) * wgt -> plain store into rank plane
    int g = lane >> 2, tig = lane & 3;
    const float* bias = b2 + (size_t)e * HDIM;
#pragma unroll
    for (int nt = 0; nt < 8; nt++) {
        int n = n0 + wn * 64 + nt * 8 + tig * 2;
        float bv0 = bias[n], bv1 = bias[n + 1];
#pragma unroll
        for (int mt = 0; mt < 4; mt++) {
#pragma unroll
            for (int half = 0; half < 2; half++) {
                int rl = wm * 64 + mt * 16 + g + half * 8;
                int m = m0 + rl;
                if (m < cnt) {
                    float w = s_wgt[rl];
                    float* dst = g_outr[s_rnk[rl]] + (size_t)s_tok[rl] * HDIM + n;
                    dst[0] = w * (acc[mt][nt][half * 2 + 0] + bv0);
                    dst[1] = w * (acc[mt][nt][half * 2 + 1] + bv1);
                }
            }
        }
    }
}

// ---------------------------------------------------------------------------
__global__ void combine_kernel(float4* __restrict__ out, long n4) {
    long i = (long)blockIdx.x * blockDim.x + threadIdx.x;
    long st = (long)gridDim.x * blockDim.x;
    const float4* r0 = (const float4*)g_outr[0];
    const float4* r1 = (const float4*)g_outr[1];
    for (; i < n4; i += st) {
        float4 a = r0[i], b = r1[i];
        out[i] = make_float4(a.x + b.x, a.y + b.y, a.z + b.z, a.w + b.w);
    }
}

// ---------------------------------------------------------------------------
extern "C" void kernel_launch(void* const* d_in, const int* in_sizes, int n_in,
                              void* d_out, int out_size) {
    const float* x  = (const float*)d_in[0];
    const float* gw = (const float*)d_in[1];
    const float* w1 = (const float*)d_in[2];
    const float* b1 = (const float*)d_in[3];
    const float* w2 = (const float*)d_in[4];
    const float* b2 = (const float*)d_in[5];
    float* out = (float*)d_out;

    cudaFuncSetAttribute(moe_gemm1, cudaFuncAttributeMaxDynamicSharedMemorySize, SMEM_TOTAL);
    cudaFuncSetAttribute(moe_gemm2, cudaFuncAttributeMaxDynamicSharedMemorySize, SMEM_TOTAL);

    reset_kernel<<<1, 32>>>();
    prep_x<<<NTOK / 8, 256>>>(x, gw);
    transpose_w<<<dim3(64, 64, 8), dim3(32, 8)>>>(w1, w2);

    moe_gemm1<<<dim3(HDIM / BN, NTOK / BM, NEXP), NTHREADS, SMEM_TOTAL>>>(b1);
    moe_gemm2<<<dim3(HDIM / BN, NTOK / BM, NEXP), NTHREADS, SMEM_TOTAL>>>(b2);
    combine_kernel<<<2048, 256>>>((float4*)out, (long)out_size / 4);
}

// round 15
// speedup vs baseline: 1.0932x; 1.0932x over previous
#include <cuda_runtime.h>
#include <cuda_fp16.h>
#include <math.h>
#include <stdint.h>

// Problem constants (B=8, S=2048, D=2048, H=2048, E=4, TOP_K=2)
#define NTOK 16384
#define DDIM 2048
#define HDIM 2048
#define NEXP 4
#define NCH  32              // K/64 chunks

// Tile config: 128M x 128N CTA, 256 threads (8 warps: 2M x 4N, 64x32 warp tile)
// 2 CTAs per SM (regs <=128, smem 97KB/CTA)
#define BM 128
#define BN 128
#define BK 64
#define NTHREADS 256
#define TILE_A 16384                        // 128 rows x 128B (64 fp16)
#define TILE_B 16384                        // 128 rows x 128B
#define STAGE_BYTES (TILE_A + TILE_B)       // 32768
#define NSTG 3
#define SMEM_TOTAL (1024 + NSTG * STAGE_BYTES) // 99328

// ---------------------------------------------------------------------------
// Scratch (static device arrays — no runtime allocation)
// ---------------------------------------------------------------------------
__device__ int   g_cnt[NEXP];
__device__ int   g_tok[NEXP][NTOK];
__device__ float g_wgt[NEXP][NTOK];
__device__ int   g_rank[NEXP][NTOK];

__device__ __align__(16) __half g_xf[(size_t)NTOK * DDIM];          // x fp16
__device__ __align__(16) __half g_w1f[(size_t)NEXP * HDIM * DDIM];  // [e][n][k]
__device__ __align__(16) __half g_w2f[(size_t)NEXP * HDIM * HDIM];
__device__ __align__(16) __half g_h1f[(size_t)NEXP * NTOK * HDIM];  // gelu out fp16
__device__ __align__(16) float  g_outr[2][(size_t)NTOK * HDIM];     // rank-split

// ---------------------------------------------------------------------------
// Helpers
// ---------------------------------------------------------------------------
__device__ __forceinline__ uint32_t smem_u32(const void* p) {
    uint32_t a;
    asm("{ .reg .u64 t; cvta.to.shared.u64 t, %1; cvt.u32.u64 %0, t; }"
        : "=r"(a) : "l"(p));
    return a;
}
// 128B-row XOR swizzle
__device__ __forceinline__ uint32_t swz(uint32_t row, uint32_t byteoff) {
    uint32_t c16 = byteoff >> 4, lo = byteoff & 15;
    return row * 128 + (((c16 ^ (row & 7)) & 7) << 4) + lo;
}
__device__ __forceinline__ void cp16(uint32_t saddr, const void* gaddr) {
    asm volatile("cp.async.cg.shared.global [%0], [%1], 16;" :: "r"(saddr), "l"(gaddr));
}
#define CP_COMMIT() asm volatile("cp.async.commit_group;" ::: "memory")
#define CP_WAIT0()  asm volatile("cp.async.wait_group 0;" ::: "memory")
#define CP_WAIT1()  asm volatile("cp.async.wait_group 1;" ::: "memory")

__device__ __forceinline__ void ldsm_x4(uint32_t* r, uint32_t addr) {
    asm volatile("ldmatrix.sync.aligned.m8n8.x4.shared.b16 {%0,%1,%2,%3}, [%4];"
        : "=r"(r[0]), "=r"(r[1]), "=r"(r[2]), "=r"(r[3]) : "r"(addr));
}
__device__ __forceinline__ void mma_f16(float* d, const uint32_t* a, const uint32_t* b) {
    asm volatile(
        "mma.sync.aligned.m16n8k16.row.col.f32.f16.f16.f32 "
        "{%0,%1,%2,%3}, {%4,%5,%6,%7}, {%8,%9}, {%0,%1,%2,%3};"
        : "+f"(d[0]), "+f"(d[1]), "+f"(d[2]), "+f"(d[3])
        : "r"(a[0]), "r"(a[1]), "r"(a[2]), "r"(a[3]), "r"(b[0]), "r"(b[1]));
}

// ---------------------------------------------------------------------------
__global__ void reset_kernel() {
    if (threadIdx.x < NEXP) g_cnt[threadIdx.x] = 0;
}

// Fused: x fp32 -> fp16 plane AND router (top-2 + renorm + per-expert lists).
__global__ void prep_x(const float* __restrict__ x, const float* __restrict__ gw) {
    int tok = blockIdx.x * 8 + (threadIdx.x >> 5);
    int lane = threadIdx.x & 31;
    const float4* src = (const float4*)(x + (size_t)tok * DDIM);
    const float4* g4 = (const float4*)gw;
    uint2* xf = (uint2*)(g_xf + (size_t)tok * DDIM);

    float a0 = 0.f, a1 = 0.f, a2 = 0.f, a3 = 0.f;
#pragma unroll
    for (int j = 0; j < 16; j++) {
        int k4 = lane + j * 32;
        float4 v = src[k4];
        float4 w0 = g4[k4], w1 = g4[512 + k4], w2 = g4[1024 + k4], w3 = g4[1536 + k4];
        a0 = fmaf(v.x, w0.x, fmaf(v.y, w0.y, fmaf(v.z, w0.z, fmaf(v.w, w0.w, a0))));
        a1 = fmaf(v.x, w1.x, fmaf(v.y, w1.y, fmaf(v.z, w1.z, fmaf(v.w, w1.w, a1))));
        a2 = fmaf(v.x, w2.x, fmaf(v.y, w2.y, fmaf(v.z, w2.z, fmaf(v.w, w2.w, a2))));
        a3 = fmaf(v.x, w3.x, fmaf(v.y, w3.y, fmaf(v.z, w3.z, fmaf(v.w, w3.w, a3))));
        __half2 p0 = __floats2half2_rn(v.x, v.y);
        __half2 p1 = __floats2half2_rn(v.z, v.w);
        xf[k4] = make_uint2(*(uint32_t*)&p0, *(uint32_t*)&p1);
    }
#pragma unroll
    for (int o = 16; o; o >>= 1) {
        a0 += __shfl_xor_sync(0xffffffffu, a0, o);
        a1 += __shfl_xor_sync(0xffffffffu, a1, o);
        a2 += __shfl_xor_sync(0xffffffffu, a2, o);
        a3 += __shfl_xor_sync(0xffffffffu, a3, o);
    }
    if (lane == 0) {
        float l[4] = {a0, a1, a2, a3};
        int i0 = 0;
#pragma unroll
        for (int e = 1; e < 4; e++) if (l[e] > l[i0]) i0 = e;
        int i1 = (i0 == 0) ? 1 : 0;
#pragma unroll
        for (int e = 0; e < 4; e++) if (e != i0 && l[e] > l[i1]) i1 = e;
        float w0 = 1.0f / (1.0f + expf(l[i1] - l[i0]));
        float w1 = 1.0f - w0;
        int s0 = atomicAdd(&g_cnt[i0], 1);
        g_tok[i0][s0] = tok; g_wgt[i0][s0] = w0; g_rank[i0][s0] = 0;
        int s1 = atomicAdd(&g_cnt[i1], 1);
        g_tok[i1][s1] = tok; g_wgt[i1][s1] = w1; g_rank[i1][s1] = 1;
    }
}

// w [E][K][N] fp32 -> wt [E][N][K] fp16; z covers both weights (0-3: w1, 4-7: w2)
__global__ void transpose_w(const float* __restrict__ w1, const float* __restrict__ w2) {
    __shared__ float tile[32][33];
    int which = blockIdx.z >> 2;
    int e = blockIdx.z & 3;
    int n0 = blockIdx.x * 32, k0 = blockIdx.y * 32;
    const float* src = (which ? w2 : w1) + (size_t)e * DDIM * HDIM;
    int tx = threadIdx.x, ty = threadIdx.y;
#pragma unroll
    for (int i = 0; i < 4; i++) {
        int k = k0 + ty + i * 8;
        tile[ty + i * 8][tx] = src[(size_t)k * HDIM + n0 + tx];
    }
    __syncthreads();
    __half* of = which ? g_w2f : g_w1f;
#pragma unroll
    for (int i = 0; i < 4; i++) {
        int n = n0 + ty + i * 8;
        float v = tile[tx][ty + i * 8];
        size_t o = ((size_t)e * HDIM + n) * DDIM + k0 + tx;
        of[o] = __float2half_rn(v);
    }
}

// ---------------------------------------------------------------------------
// GEMM core: fp16, m16n8k16, ldmatrix, 64x32 warp tile (4 mt x 4 nt).
// 8 warps: wm = wid & 1 (2 x 64 rows), wn = wid >> 1 (4 x 32 cols).
// ---------------------------------------------------------------------------
__device__ __forceinline__ void compute_chunk(uint32_t base, int wm, int wn,
                                              int lane, float acc[4][4][4]) {
    uint32_t aF = base;
    uint32_t bF = base + TILE_A;

    uint32_t a_row  = (uint32_t)(wm * 64) + (lane & 15);
    uint32_t a_kb   = (uint32_t)((lane >> 4) << 4);
    uint32_t b_row0 = (uint32_t)(wn * 32) + (((lane >> 4) & 1) << 3) + (lane & 7);
    uint32_t b_kb   = (uint32_t)(((lane >> 3) & 1) << 4);

#pragma unroll
    for (int s = 0; s < 4; s++) {
        uint32_t boff = s * 32;
        uint32_t af[4][4];
#pragma unroll
        for (int mt = 0; mt < 4; mt++)
            ldsm_x4(af[mt], aF + swz(a_row + mt * 16, boff + a_kb));
#pragma unroll
        for (int p = 0; p < 2; p++) {          // p covers n-tiles 2p, 2p+1
            uint32_t rb[4];
            ldsm_x4(rb, bF + swz(b_row0 + p * 16, boff + b_kb));
#pragma unroll
            for (int mt = 0; mt < 4; mt++) {
                mma_f16(acc[mt][2 * p],     af[mt], rb);
                mma_f16(acc[mt][2 * p + 1], af[mt], rb + 2);
            }
        }
    }
}

// ---------------------------------------------------------------------------
// GEMM1: h1[e][m][:] = gelu(x[tok] @ w1[e] + b1[e]) -> fp16
// ---------------------------------------------------------------------------
__global__ void __launch_bounds__(NTHREADS, 2)
moe_gemm1(const float* __restrict__ b1) {
    int e = blockIdx.z;
    int cnt = g_cnt[e];
    int m0 = blockIdx.y * BM;
    if (m0 >= cnt) return;
    int n0 = blockIdx.x * BN;

    __shared__ int s_tok[BM];
    extern __shared__ char dynsm[];
    uint32_t ab = (smem_u32(dynsm) + 1023) & ~1023u;

    int tid = threadIdx.x;
    int wid = tid >> 5, lane = tid & 31;
    int wm = wid & 1, wn = wid >> 1;

    if (tid < BM) {
        int s = m0 + tid; if (s > cnt - 1) s = cnt - 1;
        s_tok[tid] = g_tok[e][s];
    }
    __syncthreads();

    const __half* wf = g_w1f + (size_t)e * HDIM * DDIM;

    float acc[4][4][4];
#pragma unroll
    for (int i = 0; i < 4; i++)
#pragma unroll
        for (int j = 0; j < 4; j++)
#pragma unroll
            for (int k = 0; k < 4; k++) acc[i][j][k] = 0.f;

    int r = tid >> 3, c16 = tid & 7;           // 256 threads: 32 rows x 8 chunks
    auto load_chunk = [&](int c, uint32_t bufb) {
        int k0 = c * BK;
#pragma unroll
        for (int i = 0; i < 4; i++) {           // A: 128 rows
            int rr = r + i * 32;
            uint32_t so = swz((uint32_t)rr, (uint32_t)(c16 * 16));
            cp16(ab + bufb + so, g_xf + (size_t)s_tok[rr] * DDIM + k0 + c16 * 8);
        }
#pragma unroll
        for (int i = 0; i < 4; i++) {           // B: 128 rows
            int rr = r + i * 32;
            uint32_t so = swz((uint32_t)rr, (uint32_t)(c16 * 16));
            cp16(ab + bufb + TILE_A + so, wf + (size_t)(n0 + rr) * DDIM + k0 + c16 * 8);
        }
        CP_COMMIT();
    };

    load_chunk(0, 0);
    load_chunk(1, STAGE_BYTES);
    for (int c = 0; c < NCH; c++) {
        if (c + 1 < NCH) CP_WAIT1(); else CP_WAIT0();
        __syncthreads();
        if (c + 2 < NCH) load_chunk(c + 2, (uint32_t)((c + 2) % NSTG) * STAGE_BYTES);
        compute_chunk(ab + (uint32_t)(c % NSTG) * STAGE_BYTES, wm, wn, lane, acc);
    }

    // Epilogue: bias + exact GELU -> fp16
    int g = lane >> 2, tig = lane & 3;
    __half* h1f = g_h1f + (size_t)e * NTOK * HDIM;
    const float* bias = b1 + (size_t)e * HDIM;
#pragma unroll
    for (int nt = 0; nt < 4; nt++) {
        int n = n0 + wn * 32 + nt * 8 + tig * 2;
        float bv0 = bias[n], bv1 = bias[n + 1];
#pragma unroll
        for (int mt = 0; mt < 4; mt++) {
#pragma unroll
            for (int half = 0; half < 2; half++) {
                int m = m0 + wm * 64 + mt * 16 + g + half * 8;
                if (m < cnt) {
                    float v0 = acc[mt][nt][half * 2 + 0] + bv0;
                    float v1 = acc[mt][nt][half * 2 + 1] + bv1;
                    float g0 = 0.5f * v0 * (1.0f + erff(v0 * 0.70710678118654752f));
                    float g1 = 0.5f * v1 * (1.0f + erff(v1 * 0.70710678118654752f));
                    __half2 hv = __floats2half2_rn(g0, g1);
                    *(uint32_t*)(h1f + (size_t)m * HDIM + n) = *(uint32_t*)&hv;
                }
            }
        }
    }
}

// ---------------------------------------------------------------------------
// GEMM2: g_outr[rank][tok][:] = wgt * (h1[e] @ w2[e] + b2[e])
// ---------------------------------------------------------------------------
__global__ void __launch_bounds__(NTHREADS, 2)
moe_gemm2(const float* __restrict__ b2) {
    int e = blockIdx.z;
    int cnt = g_cnt[e];
    int m0 = blockIdx.y * BM;
    if (m0 >= cnt) return;
    int n0 = blockIdx.x * BN;

    __shared__ int   s_tok[BM];
    __shared__ float s_wgt[BM];
    __shared__ int   s_rnk[BM];
    extern __shared__ char dynsm[];
    uint32_t ab = (smem_u32(dynsm) + 1023) & ~1023u;

    int tid = threadIdx.x;
    int wid = tid >> 5, lane = tid & 31;
    int wm = wid & 1, wn = wid >> 1;

    if (tid < BM) {
        int s = m0 + tid; if (s > cnt - 1) s = cnt - 1;
        s_tok[tid] = g_tok[e][s];
        s_wgt[tid] = g_wgt[e][s];
        s_rnk[tid] = g_rank[e][s];
    }
    __syncthreads();

    const __half* ahp = g_h1f + (size_t)e * NTOK * HDIM;
    const __half* wf = g_w2f + (size_t)e * HDIM * HDIM;

    float acc[4][4][4];
#pragma unroll
    for (int i = 0; i < 4; i++)
#pragma unroll
        for (int j = 0; j < 4; j++)
#pragma unroll
            for (int k = 0; k < 4; k++) acc[i][j][k] = 0.f;

    int r = tid >> 3, c16 = tid & 7;
    auto load_chunk = [&](int c, uint32_t bufb) {
        int k0 = c * BK;
#pragma unroll
        for (int i = 0; i < 4; i++) {
            int rr = r + i * 32;
            uint32_t so = swz((uint32_t)rr, (uint32_t)(c16 * 16));
            int mm = m0 + rr; if (mm > cnt - 1) mm = cnt - 1;
            cp16(ab + bufb + so, ahp + (size_t)mm * HDIM + k0 + c16 * 8);
        }
#pragma unroll
        for (int i = 0; i < 4; i++) {
            int rr = r + i * 32;
            uint32_t so = swz((uint32_t)rr, (uint32_t)(c16 * 16));
            cp16(ab + bufb + TILE_A + so, wf + (size_t)(n0 + rr) * HDIM + k0 + c16 * 8);
        }
        CP_COMMIT();
    };

    load_chunk(0, 0);
    load_chunk(1, STAGE_BYTES);
    for (int c = 0; c < NCH; c++) {
        if (c + 1 < NCH) CP_WAIT1(); else CP_WAIT0();
        __syncthreads();
        if (c + 2 < NCH) load_chunk(c + 2, (uint32_t)((c + 2) % NSTG) * STAGE_BYTES);
        compute_chunk(ab + (uint32_t)(c % NSTG) * STAGE_BYTES, wm, wn, lane, acc);
    }

    // Epilogue: (acc + b2) * wgt -> plain store into rank plane
    int g = lane >> 2, tig = lane & 3;
    const float* bias = b2 + (size_t)e * HDIM;
#pragma unroll
    for (int nt = 0; nt < 4; nt++) {
        int n = n0 + wn * 32 + nt * 8 + tig * 2;
        float bv0 = bias[n], bv1 = bias[n + 1];
#pragma unroll
        for (int mt = 0; mt < 4; mt++) {
#pragma unroll
            for (int half = 0; half < 2; half++) {
                int rl = wm * 64 + mt * 16 + g + half * 8;
                int m = m0 + rl;
                if (m < cnt) {
                    float w = s_wgt[rl];
                    float* dst = g_outr[s_rnk[rl]] + (size_t)s_tok[rl] * HDIM + n;
                    dst[0] = w * (acc[mt][nt][half * 2 + 0] + bv0);
                    dst[1] = w * (acc[mt][nt][half * 2 + 1] + bv1);
                }
            }
        }
    }
}

// ---------------------------------------------------------------------------
__global__ void combine_kernel(float4* __restrict__ out, long n4) {
    long i = (long)blockIdx.x * blockDim.x + threadIdx.x;
    long st = (long)gridDim.x * blockDim.x;
    const float4* r0 = (const float4*)g_outr[0];
    const float4* r1 = (const float4*)g_outr[1];
    for (; i < n4; i += st) {
        float4 a = r0[i], b = r1[i];
        out[i] = make_float4(a.x + b.x, a.y + b.y, a.z + b.z, a.w + b.w);
    }
}

// ---------------------------------------------------------------------------
extern "C" void kernel_launch(void* const* d_in, const int* in_sizes, int n_in,
                              void* d_out, int out_size) {
    const float* x  = (const float*)d_in[0];
    const float* gw = (const float*)d_in[1];
    const float* w1 = (const float*)d_in[2];
    const float* b1 = (const float*)d_in[3];
    const float* w2 = (const float*)d_in[4];
    const float* b2 = (const float*)d_in[5];
    float* out = (float*)d_out;

    cudaFuncSetAttribute(moe_gemm1, cudaFuncAttributeMaxDynamicSharedMemorySize, SMEM_TOTAL);
    cudaFuncSetAttribute(moe_gemm2, cudaFuncAttributeMaxDynamicSharedMemorySize, SMEM_TOTAL);

    reset_kernel<<<1, 32>>>();
    prep_x<<<NTOK / 8, 256>>>(x, gw);
    transpose_w<<<dim3(64, 64, 8), dim3(32, 8)>>>(w1, w2);

    moe_gemm1<<<dim3(HDIM / BN, NTOK / BM, NEXP), NTHREADS, SMEM_TOTAL>>>(b1);
    moe_gemm2<<<dim3(HDIM / BN, NTOK / BM, NEXP), NTHREADS, SMEM_TOTAL>>>(b2);
    combine_kernel<<<2048, 256>>>((float4*)out, (long)out_size / 4);
}

// round 16
// speedup vs baseline: 1.0997x; 1.0059x over previous
#include <cuda_runtime.h>
#include <cuda_fp16.h>
#include <math.h>
#include <stdint.h>

// Problem constants (B=8, S=2048, D=2048, H=2048, E=4, TOP_K=2)
#define NTOK 16384
#define DDIM 2048
#define HDIM 2048
#define NEXP 4
#define NCH  32              // K/64 chunks

// Tile config: 128M x 128N CTA, 256 threads (8 warps: 2M x 4N, 64x32 warp tile)
// 2 CTAs per SM (regs <=128, smem 97KB/CTA)
#define BM 128
#define BN 128
#define BK 64
#define NTHREADS 256
#define TILE_A 16384                        // 128 rows x 128B (64 fp16)
#define TILE_B 16384                        // 128 rows x 128B
#define STAGE_BYTES (TILE_A + TILE_B)       // 32768
#define NSTG 3
#define SMEM_TOTAL (1024 + NSTG * STAGE_BYTES) // 99328

// ---------------------------------------------------------------------------
// Scratch (static device arrays — no runtime allocation)
// ---------------------------------------------------------------------------
__device__ int   g_cnt[NEXP];
__device__ int   g_tok[NEXP][NTOK];
__device__ float g_wgt[NEXP][NTOK];
__device__ int   g_rank[NEXP][NTOK];

__device__ __align__(16) __half g_xf[(size_t)NTOK * DDIM];          // x fp16
__device__ __align__(16) __half g_w1f[(size_t)NEXP * HDIM * DDIM];  // [e][n][k]
__device__ __align__(16) __half g_w2f[(size_t)NEXP * HDIM * HDIM];
__device__ __align__(16) __half g_h1f[(size_t)NEXP * NTOK * HDIM];  // gelu out fp16
__device__ __align__(16) float  g_outr[2][(size_t)NTOK * HDIM];     // rank-split

// ---------------------------------------------------------------------------
// Helpers
// ---------------------------------------------------------------------------
__device__ __forceinline__ uint32_t smem_u32(const void* p) {
    uint32_t a;
    asm("{ .reg .u64 t; cvta.to.shared.u64 t, %1; cvt.u32.u64 %0, t; }"
        : "=r"(a) : "l"(p));
    return a;
}
// 128B-row XOR swizzle
__device__ __forceinline__ uint32_t swz(uint32_t row, uint32_t byteoff) {
    uint32_t c16 = byteoff >> 4, lo = byteoff & 15;
    return row * 128 + (((c16 ^ (row & 7)) & 7) << 4) + lo;
}
__device__ __forceinline__ void cp16(uint32_t saddr, const void* gaddr) {
    asm volatile("cp.async.cg.shared.global [%0], [%1], 16;" :: "r"(saddr), "l"(gaddr));
}
#define CP_COMMIT() asm volatile("cp.async.commit_group;" ::: "memory")
#define CP_WAIT0()  asm volatile("cp.async.wait_group 0;" ::: "memory")
#define CP_WAIT1()  asm volatile("cp.async.wait_group 1;" ::: "memory")

__device__ __forceinline__ void ldsm_x4(uint32_t* r, uint32_t addr) {
    asm volatile("ldmatrix.sync.aligned.m8n8.x4.shared.b16 {%0,%1,%2,%3}, [%4];"
        : "=r"(r[0]), "=r"(r[1]), "=r"(r[2]), "=r"(r[3]) : "r"(addr));
}
__device__ __forceinline__ void mma_f16(float* d, const uint32_t* a, const uint32_t* b) {
    asm volatile(
        "mma.sync.aligned.m16n8k16.row.col.f32.f16.f16.f32 "
        "{%0,%1,%2,%3}, {%4,%5,%6,%7}, {%8,%9}, {%0,%1,%2,%3};"
        : "+f"(d[0]), "+f"(d[1]), "+f"(d[2]), "+f"(d[3])
        : "r"(a[0]), "r"(a[1]), "r"(a[2]), "r"(a[3]), "r"(b[0]), "r"(b[1]));
}

// ---------------------------------------------------------------------------
__global__ void reset_kernel() {
    if (threadIdx.x < NEXP) g_cnt[threadIdx.x] = 0;
}

// Fused: x fp32 -> fp16 plane AND router (top-2 + renorm + per-expert lists).
__global__ void prep_x(const float* __restrict__ x, const float* __restrict__ gw) {
    int tok = blockIdx.x * 8 + (threadIdx.x >> 5);
    int lane = threadIdx.x & 31;
    const float4* src = (const float4*)(x + (size_t)tok * DDIM);
    const float4* g4 = (const float4*)gw;
    uint2* xf = (uint2*)(g_xf + (size_t)tok * DDIM);

    float a0 = 0.f, a1 = 0.f, a2 = 0.f, a3 = 0.f;
#pragma unroll
    for (int j = 0; j < 16; j++) {
        int k4 = lane + j * 32;
        float4 v = src[k4];
        float4 w0 = g4[k4], w1 = g4[512 + k4], w2 = g4[1024 + k4], w3 = g4[1536 + k4];
        a0 = fmaf(v.x, w0.x, fmaf(v.y, w0.y, fmaf(v.z, w0.z, fmaf(v.w, w0.w, a0))));
        a1 = fmaf(v.x, w1.x, fmaf(v.y, w1.y, fmaf(v.z, w1.z, fmaf(v.w, w1.w, a1))));
        a2 = fmaf(v.x, w2.x, fmaf(v.y, w2.y, fmaf(v.z, w2.z, fmaf(v.w, w2.w, a2))));
        a3 = fmaf(v.x, w3.x, fmaf(v.y, w3.y, fmaf(v.z, w3.z, fmaf(v.w, w3.w, a3))));
        __half2 p0 = __floats2half2_rn(v.x, v.y);
        __half2 p1 = __floats2half2_rn(v.z, v.w);
        xf[k4] = make_uint2(*(uint32_t*)&p0, *(uint32_t*)&p1);
    }
#pragma unroll
    for (int o = 16; o; o >>= 1) {
        a0 += __shfl_xor_sync(0xffffffffu, a0, o);
        a1 += __shfl_xor_sync(0xffffffffu, a1, o);
        a2 += __shfl_xor_sync(0xffffffffu, a2, o);
        a3 += __shfl_xor_sync(0xffffffffu, a3, o);
    }
    if (lane == 0) {
        float l[4] = {a0, a1, a2, a3};
        int i0 = 0;
#pragma unroll
        for (int e = 1; e < 4; e++) if (l[e] > l[i0]) i0 = e;
        int i1 = (i0 == 0) ? 1 : 0;
#pragma unroll
        for (int e = 0; e < 4; e++) if (e != i0 && l[e] > l[i1]) i1 = e;
        float w0 = 1.0f / (1.0f + expf(l[i1] - l[i0]));
        float w1 = 1.0f - w0;
        int s0 = atomicAdd(&g_cnt[i0], 1);
        g_tok[i0][s0] = tok; g_wgt[i0][s0] = w0; g_rank[i0][s0] = 0;
        int s1 = atomicAdd(&g_cnt[i1], 1);
        g_tok[i1][s1] = tok; g_wgt[i1][s1] = w1; g_rank[i1][s1] = 1;
    }
}

// w [E][K][N] fp32 -> wt [E][N][K] fp16; z covers both weights (0-3: w1, 4-7: w2)
__global__ void transpose_w(const float* __restrict__ w1, const float* __restrict__ w2) {
    __shared__ float tile[32][33];
    int which = blockIdx.z >> 2;
    int e = blockIdx.z & 3;
    int n0 = blockIdx.x * 32, k0 = blockIdx.y * 32;
    const float* src = (which ? w2 : w1) + (size_t)e * DDIM * HDIM;
    int tx = threadIdx.x, ty = threadIdx.y;
#pragma unroll
    for (int i = 0; i < 4; i++) {
        int k = k0 + ty + i * 8;
        tile[ty + i * 8][tx] = src[(size_t)k * HDIM + n0 + tx];
    }
    __syncthreads();
    __half* of = which ? g_w2f : g_w1f;
#pragma unroll
    for (int i = 0; i < 4; i++) {
        int n = n0 + ty + i * 8;
        float v = tile[tx][ty + i * 8];
        size_t o = ((size_t)e * HDIM + n) * DDIM + k0 + tx;
        of[o] = __float2half_rn(v);
    }
}

// ---------------------------------------------------------------------------
// GEMM core: fp16, m16n8k16, ldmatrix, 64x32 warp tile (4 mt x 4 nt).
// B fragments double-buffered: B(s+1) ldsm issued before the 16 MMAs of s.
// A fragments loaded at the top of each s (before B(s+1)), so their RAW gap
// spans 2 trailing ldsm + warp interleave.
// 8 warps: wm = wid & 1 (2 x 64 rows), wn = wid >> 1 (4 x 32 cols).
// ---------------------------------------------------------------------------
__device__ __forceinline__ void compute_chunk(uint32_t base, int wm, int wn,
                                              int lane, float acc[4][4][4]) {
    uint32_t aF = base;
    uint32_t bF = base + TILE_A;

    uint32_t a_row  = (uint32_t)(wm * 64) + (lane & 15);
    uint32_t a_kb   = (uint32_t)((lane >> 4) << 4);
    uint32_t b_row0 = (uint32_t)(wn * 32) + (((lane >> 4) & 1) << 3) + (lane & 7);
    uint32_t b_kb   = (uint32_t)(((lane >> 3) & 1) << 4);

    uint32_t rb[2][2][4];
#pragma unroll
    for (int p = 0; p < 2; p++)
        ldsm_x4(rb[0][p], bF + swz(b_row0 + p * 16, b_kb));

#pragma unroll
    for (int s = 0; s < 4; s++) {
        int cur = s & 1;
        uint32_t boff = (uint32_t)s * 32;
        uint32_t af[4][4];
#pragma unroll
        for (int mt = 0; mt < 4; mt++)
            ldsm_x4(af[mt], aF + swz(a_row + mt * 16, boff + a_kb));
        if (s < 3) {
            uint32_t bnx = boff + 32;
#pragma unroll
            for (int p = 0; p < 2; p++)
                ldsm_x4(rb[cur ^ 1][p], bF + swz(b_row0 + p * 16, bnx + b_kb));
        }
#pragma unroll
        for (int p = 0; p < 2; p++) {
#pragma unroll
            for (int mt = 0; mt < 4; mt++) {
                mma_f16(acc[mt][2 * p],     af[mt], rb[cur][p]);
                mma_f16(acc[mt][2 * p + 1], af[mt], rb[cur][p] + 2);
            }
        }
    }
}

// ---------------------------------------------------------------------------
// GEMM1: h1[e][m][:] = gelu(x[tok] @ w1[e] + b1[e]) -> fp16
// ---------------------------------------------------------------------------
__global__ void __launch_bounds__(NTHREADS, 2)
moe_gemm1(const float* __restrict__ b1) {
    int e = blockIdx.z;
    int cnt = g_cnt[e];
    int m0 = blockIdx.y * BM;
    if (m0 >= cnt) return;
    int n0 = blockIdx.x * BN;

    __shared__ int s_tok[BM];
    extern __shared__ char dynsm[];
    uint32_t ab = (smem_u32(dynsm) + 1023) & ~1023u;

    int tid = threadIdx.x;
    int wid = tid >> 5, lane = tid & 31;
    int wm = wid & 1, wn = wid >> 1;

    if (tid < BM) {
        int s = m0 + tid; if (s > cnt - 1) s = cnt - 1;
        s_tok[tid] = g_tok[e][s];
    }
    __syncthreads();

    const __half* wf = g_w1f + (size_t)e * HDIM * DDIM;

    float acc[4][4][4];
#pragma unroll
    for (int i = 0; i < 4; i++)
#pragma unroll
        for (int j = 0; j < 4; j++)
#pragma unroll
            for (int k = 0; k < 4; k++) acc[i][j][k] = 0.f;

    int r = tid >> 3, c16 = tid & 7;           // 256 threads: 32 rows x 8 chunks
    auto load_chunk = [&](int c, uint32_t bufb) {
        int k0 = c * BK;
#pragma unroll
        for (int i = 0; i < 4; i++) {           // A: 128 rows
            int rr = r + i * 32;
            uint32_t so = swz((uint32_t)rr, (uint32_t)(c16 * 16));
            cp16(ab + bufb + so, g_xf + (size_t)s_tok[rr] * DDIM + k0 + c16 * 8);
        }
#pragma unroll
        for (int i = 0; i < 4; i++) {           // B: 128 rows
            int rr = r + i * 32;
            uint32_t so = swz((uint32_t)rr, (uint32_t)(c16 * 16));
            cp16(ab + bufb + TILE_A + so, wf + (size_t)(n0 + rr) * DDIM + k0 + c16 * 8);
        }
        CP_COMMIT();
    };

    load_chunk(0, 0);
    load_chunk(1, STAGE_BYTES);
    for (int c = 0; c < NCH; c++) {
        if (c + 1 < NCH) CP_WAIT1(); else CP_WAIT0();
        __syncthreads();
        if (c + 2 < NCH) load_chunk(c + 2, (uint32_t)((c + 2) % NSTG) * STAGE_BYTES);
        compute_chunk(ab + (uint32_t)(c % NSTG) * STAGE_BYTES, wm, wn, lane, acc);
    }

    // Epilogue: bias + exact GELU -> fp16
    int g = lane >> 2, tig = lane & 3;
    __half* h1f = g_h1f + (size_t)e * NTOK * HDIM;
    const float* bias = b1 + (size_t)e * HDIM;
#pragma unroll
    for (int nt = 0; nt < 4; nt++) {
        int n = n0 + wn * 32 + nt * 8 + tig * 2;
        float bv0 = bias[n], bv1 = bias[n + 1];
#pragma unroll
        for (int mt = 0; mt < 4; mt++) {
#pragma unroll
            for (int half = 0; half < 2; half++) {
                int m = m0 + wm * 64 + mt * 16 + g + half * 8;
                if (m < cnt) {
                    float v0 = acc[mt][nt][half * 2 + 0] + bv0;
                    float v1 = acc[mt][nt][half * 2 + 1] + bv1;
                    float g0 = 0.5f * v0 * (1.0f + erff(v0 * 0.70710678118654752f));
                    float g1 = 0.5f * v1 * (1.0f + erff(v1 * 0.70710678118654752f));
                    __half2 hv = __floats2half2_rn(g0, g1);
                    *(uint32_t*)(h1f + (size_t)m * HDIM + n) = *(uint32_t*)&hv;
                }
            }
        }
    }
}

// ---------------------------------------------------------------------------
// GEMM2: g_outr[rank][tok][:] = wgt * (h1[e] @ w2[e] + b2[e])
// ---------------------------------------------------------------------------
__global__ void __launch_bounds__(NTHREADS, 2)
moe_gemm2(const float* __restrict__ b2) {
    int e = blockIdx.z;
    int cnt = g_cnt[e];
    int m0 = blockIdx.y * BM;
    if (m0 >= cnt) return;
    int n0 = blockIdx.x * BN;

    __shared__ int   s_tok[BM];
    __shared__ float s_wgt[BM];
    __shared__ int   s_rnk[BM];
    extern __shared__ char dynsm[];
    uint32_t ab = (smem_u32(dynsm) + 1023) & ~1023u;

    int tid = threadIdx.x;
    int wid = tid >> 5, lane = tid & 31;
    int wm = wid & 1, wn = wid >> 1;

    if (tid < BM) {
        int s = m0 + tid; if (s > cnt - 1) s = cnt - 1;
        s_tok[tid] = g_tok[e][s];
        s_wgt[tid] = g_wgt[e][s];
        s_rnk[tid] = g_rank[e][s];
    }
    __syncthreads();

    const __half* ahp = g_h1f + (size_t)e * NTOK * HDIM;
    const __half* wf = g_w2f + (size_t)e * HDIM * HDIM;

    float acc[4][4][4];
#pragma unroll
    for (int i = 0; i < 4; i++)
#pragma unroll
        for (int j = 0; j < 4; j++)
#pragma unroll
            for (int k = 0; k < 4; k++) acc[i][j][k] = 0.f;

    int r = tid >> 3, c16 = tid & 7;
    auto load_chunk = [&](int c, uint32_t bufb) {
        int k0 = c * BK;
#pragma unroll
        for (int i = 0; i < 4; i++) {
            int rr = r + i * 32;
            uint32_t so = swz((uint32_t)rr, (uint32_t)(c16 * 16));
            int mm = m0 + rr; if (mm > cnt - 1) mm = cnt - 1;
            cp16(ab + bufb + so, ahp + (size_t)mm * HDIM + k0 + c16 * 8);
        }
#pragma unroll
        for (int i = 0; i < 4; i++) {
            int rr = r + i * 32;
            uint32_t so = swz((uint32_t)rr, (uint32_t)(c16 * 16));
            cp16(ab + bufb + TILE_A + so, wf + (size_t)(n0 + rr) * HDIM + k0 + c16 * 8);
        }
        CP_COMMIT();
    };

    load_chunk(0, 0);
    load_chunk(1, STAGE_BYTES);
    for (int c = 0; c < NCH; c++) {
        if (c + 1 < NCH) CP_WAIT1(); else CP_WAIT0();
        __syncthreads();
        if (c + 2 < NCH) load_chunk(c + 2, (uint32_t)((c + 2) % NSTG) * STAGE_BYTES);
        compute_chunk(ab + (uint32_t)(c % NSTG) * STAGE_BYTES, wm, wn, lane, acc);
    }

    // Epilogue: (acc + b2) * wgt -> plain store into rank plane
    int g = lane >> 2, tig = lane & 3;
    const float* bias = b2 + (size_t)e * HDIM;
#pragma unroll
    for (int nt = 0; nt < 4; nt++) {
        int n = n0 + wn * 32 + nt * 8 + tig * 2;
        float bv0 = bias[n], bv1 = bias[n + 1];
#pragma unroll
        for (int mt = 0; mt < 4; mt++) {
#pragma unroll
            for (int half = 0; half < 2; half++) {
                int rl = wm * 64 + mt * 16 + g + half * 8;
                int m = m0 + rl;
                if (m < cnt) {
                    float w = s_wgt[rl];
                    float* dst = g_outr[s_rnk[rl]] + (size_t)s_tok[rl] * HDIM + n;
                    dst[0] = w * (acc[mt][nt][half * 2 + 0] + bv0);
                    dst[1] = w * (acc[mt][nt][half * 2 + 1] + bv1);
                }
            }
        }
    }
}

// ---------------------------------------------------------------------------
__global__ void combine_kernel(float4* __restrict__ out, long n4) {
    long i = (long)blockIdx.x * blockDim.x + threadIdx.x;
    long st = (long)gridDim.x * blockDim.x;
    const float4* r0 = (const float4*)g_outr[0];
    const float4* r1 = (const float4*)g_outr[1];
    for (; i < n4; i += st) {
        float4 a = r0[i], b = r1[i];
        out[i] = make_float4(a.x + b.x, a.y + b.y, a.z + b.z, a.w + b.w);
    }
}

// ---------------------------------------------------------------------------
extern "C" void kernel_launch(void* const* d_in, const int* in_sizes, int n_in,
                              void* d_out, int out_size) {
    const float* x  = (const float*)d_in[0];
    const float* gw = (const float*)d_in[1];
    const float* w1 = (const float*)d_in[2];
    const float* b1 = (const float*)d_in[3];
    const float* w2 = (const float*)d_in[4];
    const float* b2 = (const float*)d_in[5];
    float* out = (float*)d_out;

    cudaFuncSetAttribute(moe_gemm1, cudaFuncAttributeMaxDynamicSharedMemorySize, SMEM_TOTAL);
    cudaFuncSetAttribute(moe_gemm2, cudaFuncAttributeMaxDynamicSharedMemorySize, SMEM_TOTAL);

    reset_kernel<<<1, 32>>>();
    prep_x<<<NTOK / 8, 256>>>(x, gw);
    transpose_w<<<dim3(64, 64, 8), dim3(32, 8)>>>(w1, w2);

    moe_gemm1<<<dim3(HDIM / BN, NTOK / BM, NEXP), NTHREADS, SMEM_TOTAL>>>(b1);
    moe_gemm2<<<dim3(HDIM / BN, NTOK / BM, NEXP), NTHREADS, SMEM_TOTAL>>>(b2);
    combine_kernel<<<2048, 256>>>((float4*)out, (long)out_size / 4);
}

// round 17
// speedup vs baseline: 1.1085x; 1.0080x over previous
#include <cuda_runtime.h>
#include <cuda_fp16.h>
#include <math.h>
#include <stdint.h>

// Problem constants (B=8, S=2048, D=2048, H=2048, E=4, TOP_K=2)
#define NTOK 16384
#define DDIM 2048
#define HDIM 2048
#define NEXP 4
#define NCH  32              // K/64 chunks

// Tile config: 128M x 128N CTA, 256 threads (8 warps: 2M x 4N, 64x32 warp tile)
// 2 CTAs per SM (regs <=128, smem 97KB/CTA)
#define BM 128
#define BN 128
#define BK 64
#define NTHREADS 256
#define TILE_A 16384                        // 128 rows x 128B (64 fp16)
#define TILE_B 16384                        // 128 rows x 128B
#define STAGE_BYTES (TILE_A + TILE_B)       // 32768
#define NSTG 3
#define SMEM_TOTAL (1024 + NSTG * STAGE_BYTES) // 99328

// ---------------------------------------------------------------------------
// Scratch (static device arrays — no runtime allocation)
// ---------------------------------------------------------------------------
__device__ int   g_cnt[NEXP];
__device__ int   g_tok[NEXP][NTOK];
__device__ float g_wgt[NEXP][NTOK];
__device__ int   g_rank[NEXP][NTOK];

__device__ __align__(16) __half g_xf[(size_t)NTOK * DDIM];          // x fp16
__device__ __align__(16) __half g_w1f[(size_t)NEXP * HDIM * DDIM];  // [e][n][k]
__device__ __align__(16) __half g_w2f[(size_t)NEXP * HDIM * HDIM];
__device__ __align__(16) __half g_h1f[(size_t)NEXP * NTOK * HDIM];  // gelu out fp16
__device__ __align__(16) __half g_outr[2][(size_t)NTOK * HDIM];     // rank-split fp16

// ---------------------------------------------------------------------------
// Helpers
// ---------------------------------------------------------------------------
__device__ __forceinline__ uint32_t smem_u32(const void* p) {
    uint32_t a;
    asm("{ .reg .u64 t; cvta.to.shared.u64 t, %1; cvt.u32.u64 %0, t; }"
        : "=r"(a) : "l"(p));
    return a;
}
// 128B-row XOR swizzle
__device__ __forceinline__ uint32_t swz(uint32_t row, uint32_t byteoff) {
    uint32_t c16 = byteoff >> 4, lo = byteoff & 15;
    return row * 128 + (((c16 ^ (row & 7)) & 7) << 4) + lo;
}
__device__ __forceinline__ void cp16(uint32_t saddr, const void* gaddr) {
    asm volatile("cp.async.cg.shared.global [%0], [%1], 16;" :: "r"(saddr), "l"(gaddr));
}
#define CP_COMMIT() asm volatile("cp.async.commit_group;" ::: "memory")
#define CP_WAIT0()  asm volatile("cp.async.wait_group 0;" ::: "memory")
#define CP_WAIT1()  asm volatile("cp.async.wait_group 1;" ::: "memory")

__device__ __forceinline__ void ldsm_x4(uint32_t* r, uint32_t addr) {
    asm volatile("ldmatrix.sync.aligned.m8n8.x4.shared.b16 {%0,%1,%2,%3}, [%4];"
        : "=r"(r[0]), "=r"(r[1]), "=r"(r[2]), "=r"(r[3]) : "r"(addr));
}
__device__ __forceinline__ void mma_f16(float* d, const uint32_t* a, const uint32_t* b) {
    asm volatile(
        "mma.sync.aligned.m16n8k16.row.col.f32.f16.f16.f32 "
        "{%0,%1,%2,%3}, {%4,%5,%6,%7}, {%8,%9}, {%0,%1,%2,%3};"
        : "+f"(d[0]), "+f"(d[1]), "+f"(d[2]), "+f"(d[3])
        : "r"(a[0]), "r"(a[1]), "r"(a[2]), "r"(a[3]), "r"(b[0]), "r"(b[1]));
}

// ---------------------------------------------------------------------------
__global__ void reset_kernel() {
    if (threadIdx.x < NEXP) g_cnt[threadIdx.x] = 0;
}

// Fused: x fp32 -> fp16 plane AND router (top-2 + renorm + per-expert lists).
__global__ void prep_x(const float* __restrict__ x, const float* __restrict__ gw) {
    int tok = blockIdx.x * 8 + (threadIdx.x >> 5);
    int lane = threadIdx.x & 31;
    const float4* src = (const float4*)(x + (size_t)tok * DDIM);
    const float4* g4 = (const float4*)gw;
    uint2* xf = (uint2*)(g_xf + (size_t)tok * DDIM);

    float a0 = 0.f, a1 = 0.f, a2 = 0.f, a3 = 0.f;
#pragma unroll
    for (int j = 0; j < 16; j++) {
        int k4 = lane + j * 32;
        float4 v = src[k4];
        float4 w0 = g4[k4], w1 = g4[512 + k4], w2 = g4[1024 + k4], w3 = g4[1536 + k4];
        a0 = fmaf(v.x, w0.x, fmaf(v.y, w0.y, fmaf(v.z, w0.z, fmaf(v.w, w0.w, a0))));
        a1 = fmaf(v.x, w1.x, fmaf(v.y, w1.y, fmaf(v.z, w1.z, fmaf(v.w, w1.w, a1))));
        a2 = fmaf(v.x, w2.x, fmaf(v.y, w2.y, fmaf(v.z, w2.z, fmaf(v.w, w2.w, a2))));
        a3 = fmaf(v.x, w3.x, fmaf(v.y, w3.y, fmaf(v.z, w3.z, fmaf(v.w, w3.w, a3))));
        __half2 p0 = __floats2half2_rn(v.x, v.y);
        __half2 p1 = __floats2half2_rn(v.z, v.w);
        xf[k4] = make_uint2(*(uint32_t*)&p0, *(uint32_t*)&p1);
    }
#pragma unroll
    for (int o = 16; o; o >>= 1) {
        a0 += __shfl_xor_sync(0xffffffffu, a0, o);
        a1 += __shfl_xor_sync(0xffffffffu, a1, o);
        a2 += __shfl_xor_sync(0xffffffffu, a2, o);
        a3 += __shfl_xor_sync(0xffffffffu, a3, o);
    }
    if (lane == 0) {
        float l[4] = {a0, a1, a2, a3};
        int i0 = 0;
#pragma unroll
        for (int e = 1; e < 4; e++) if (l[e] > l[i0]) i0 = e;
        int i1 = (i0 == 0) ? 1 : 0;
#pragma unroll
        for (int e = 0; e < 4; e++) if (e != i0 && l[e] > l[i1]) i1 = e;
        float w0 = 1.0f / (1.0f + expf(l[i1] - l[i0]));
        float w1 = 1.0f - w0;
        int s0 = atomicAdd(&g_cnt[i0], 1);
        g_tok[i0][s0] = tok; g_wgt[i0][s0] = w0; g_rank[i0][s0] = 0;
        int s1 = atomicAdd(&g_cnt[i1], 1);
        g_tok[i1][s1] = tok; g_wgt[i1][s1] = w1; g_rank[i1][s1] = 1;
    }
}

// w [E][K][N] fp32 -> wt [E][N][K] fp16; z covers both weights (0-3: w1, 4-7: w2)
__global__ void transpose_w(const float* __restrict__ w1, const float* __restrict__ w2) {
    __shared__ float tile[32][33];
    int which = blockIdx.z >> 2;
    int e = blockIdx.z & 3;
    int n0 = blockIdx.x * 32, k0 = blockIdx.y * 32;
    const float* src = (which ? w2 : w1) + (size_t)e * DDIM * HDIM;
    int tx = threadIdx.x, ty = threadIdx.y;
#pragma unroll
    for (int i = 0; i < 4; i++) {
        int k = k0 + ty + i * 8;
        tile[ty + i * 8][tx] = src[(size_t)k * HDIM + n0 + tx];
    }
    __syncthreads();
    __half* of = which ? g_w2f : g_w1f;
#pragma unroll
    for (int i = 0; i < 4; i++) {
        int n = n0 + ty + i * 8;
        float v = tile[tx][ty + i * 8];
        size_t o = ((size_t)e * HDIM + n) * DDIM + k0 + tx;
        of[o] = __float2half_rn(v);
    }
}

// ---------------------------------------------------------------------------
// GEMM core: fp16, m16n8k16, ldmatrix, 64x32 warp tile (4 mt x 4 nt).
// B fragments double-buffered (proven R16 config).
// 8 warps: wm = wid & 1 (2 x 64 rows), wn = wid >> 1 (4 x 32 cols).
// ---------------------------------------------------------------------------
__device__ __forceinline__ void compute_chunk(uint32_t base, int wm, int wn,
                                              int lane, float acc[4][4][4]) {
    uint32_t aF = base;
    uint32_t bF = base + TILE_A;

    uint32_t a_row  = (uint32_t)(wm * 64) + (lane & 15);
    uint32_t a_kb   = (uint32_t)((lane >> 4) << 4);
    uint32_t b_row0 = (uint32_t)(wn * 32) + (((lane >> 4) & 1) << 3) + (lane & 7);
    uint32_t b_kb   = (uint32_t)(((lane >> 3) & 1) << 4);

    uint32_t rb[2][2][4];
#pragma unroll
    for (int p = 0; p < 2; p++)
        ldsm_x4(rb[0][p], bF + swz(b_row0 + p * 16, b_kb));

#pragma unroll
    for (int s = 0; s < 4; s++) {
        int cur = s & 1;
        uint32_t boff = (uint32_t)s * 32;
        uint32_t af[4][4];
#pragma unroll
        for (int mt = 0; mt < 4; mt++)
            ldsm_x4(af[mt], aF + swz(a_row + mt * 16, boff + a_kb));
        if (s < 3) {
            uint32_t bnx = boff + 32;
#pragma unroll
            for (int p = 0; p < 2; p++)
                ldsm_x4(rb[cur ^ 1][p], bF + swz(b_row0 + p * 16, bnx + b_kb));
        }
#pragma unroll
        for (int p = 0; p < 2; p++) {
#pragma unroll
            for (int mt = 0; mt < 4; mt++) {
                mma_f16(acc[mt][2 * p],     af[mt], rb[cur][p]);
                mma_f16(acc[mt][2 * p + 1], af[mt], rb[cur][p] + 2);
            }
        }
    }
}

// ---------------------------------------------------------------------------
// GEMM1: h1[e][m][:] = gelu(x[tok] @ w1[e] + b1[e]) -> fp16
// ---------------------------------------------------------------------------
__global__ void __launch_bounds__(NTHREADS, 2)
moe_gemm1(const float* __restrict__ b1) {
    int e = blockIdx.z;
    int cnt = g_cnt[e];
    int m0 = blockIdx.y * BM;
    if (m0 >= cnt) return;
    int n0 = blockIdx.x * BN;

    __shared__ int s_tok[BM];
    extern __shared__ char dynsm[];
    uint32_t ab = (smem_u32(dynsm) + 1023) & ~1023u;

    int tid = threadIdx.x;
    int wid = tid >> 5, lane = tid & 31;
    int wm = wid & 1, wn = wid >> 1;

    if (tid < BM) {
        int s = m0 + tid; if (s > cnt - 1) s = cnt - 1;
        s_tok[tid] = g_tok[e][s];
    }
    __syncthreads();

    const __half* wf = g_w1f + (size_t)e * HDIM * DDIM;

    float acc[4][4][4];
#pragma unroll
    for (int i = 0; i < 4; i++)
#pragma unroll
        for (int j = 0; j < 4; j++)
#pragma unroll
            for (int k = 0; k < 4; k++) acc[i][j][k] = 0.f;

    int r = tid >> 3, c16 = tid & 7;           // 256 threads: 32 rows x 8 chunks
    auto load_chunk = [&](int c, uint32_t bufb) {
        int k0 = c * BK;
#pragma unroll
        for (int i = 0; i < 4; i++) {           // A: 128 rows
            int rr = r + i * 32;
            uint32_t so = swz((uint32_t)rr, (uint32_t)(c16 * 16));
            cp16(ab + bufb + so, g_xf + (size_t)s_tok[rr] * DDIM + k0 + c16 * 8);
        }
#pragma unroll
        for (int i = 0; i < 4; i++) {           // B: 128 rows
            int rr = r + i * 32;
            uint32_t so = swz((uint32_t)rr, (uint32_t)(c16 * 16));
            cp16(ab + bufb + TILE_A + so, wf + (size_t)(n0 + rr) * DDIM + k0 + c16 * 8);
        }
        CP_COMMIT();
    };

    load_chunk(0, 0);
    load_chunk(1, STAGE_BYTES);
    for (int c = 0; c < NCH; c++) {
        if (c + 1 < NCH) CP_WAIT1(); else CP_WAIT0();
        __syncthreads();
        if (c + 2 < NCH) load_chunk(c + 2, (uint32_t)((c + 2) % NSTG) * STAGE_BYTES);
        compute_chunk(ab + (uint32_t)(c % NSTG) * STAGE_BYTES, wm, wn, lane, acc);
    }

    // Epilogue: bias + exact GELU -> fp16
    int g = lane >> 2, tig = lane & 3;
    __half* h1f = g_h1f + (size_t)e * NTOK * HDIM;
    const float* bias = b1 + (size_t)e * HDIM;
#pragma unroll
    for (int nt = 0; nt < 4; nt++) {
        int n = n0 + wn * 32 + nt * 8 + tig * 2;
        float bv0 = bias[n], bv1 = bias[n + 1];
#pragma unroll
        for (int mt = 0; mt < 4; mt++) {
#pragma unroll
            for (int half = 0; half < 2; half++) {
                int m = m0 + wm * 64 + mt * 16 + g + half * 8;
                if (m < cnt) {
                    float v0 = acc[mt][nt][half * 2 + 0] + bv0;
                    float v1 = acc[mt][nt][half * 2 + 1] + bv1;
                    float g0 = 0.5f * v0 * (1.0f + erff(v0 * 0.70710678118654752f));
                    float g1 = 0.5f * v1 * (1.0f + erff(v1 * 0.70710678118654752f));
                    __half2 hv = __floats2half2_rn(g0, g1);
                    *(uint32_t*)(h1f + (size_t)m * HDIM + n) = *(uint32_t*)&hv;
                }
            }
        }
    }
}

// ---------------------------------------------------------------------------
// GEMM2: g_outr[rank][tok][:] = fp16( wgt * (h1[e] @ w2[e] + b2[e]) )
// ---------------------------------------------------------------------------
__global__ void __launch_bounds__(NTHREADS, 2)
moe_gemm2(const float* __restrict__ b2) {
    int e = blockIdx.z;
    int cnt = g_cnt[e];
    int m0 = blockIdx.y * BM;
    if (m0 >= cnt) return;
    int n0 = blockIdx.x * BN;

    __shared__ int   s_tok[BM];
    __shared__ float s_wgt[BM];
    __shared__ int   s_rnk[BM];
    extern __shared__ char dynsm[];
    uint32_t ab = (smem_u32(dynsm) + 1023) & ~1023u;

    int tid = threadIdx.x;
    int wid = tid >> 5, lane = tid & 31;
    int wm = wid & 1, wn = wid >> 1;

    if (tid < BM) {
        int s = m0 + tid; if (s > cnt - 1) s = cnt - 1;
        s_tok[tid] = g_tok[e][s];
        s_wgt[tid] = g_wgt[e][s];
        s_rnk[tid] = g_rank[e][s];
    }
    __syncthreads();

    const __half* ahp = g_h1f + (size_t)e * NTOK * HDIM;
    const __half* wf = g_w2f + (size_t)e * HDIM * HDIM;

    float acc[4][4][4];
#pragma unroll
    for (int i = 0; i < 4; i++)
#pragma unroll
        for (int j = 0; j < 4; j++)
#pragma unroll
            for (int k = 0; k < 4; k++) acc[i][j][k] = 0.f;

    int r = tid >> 3, c16 = tid & 7;
    auto load_chunk = [&](int c, uint32_t bufb) {
        int k0 = c * BK;
#pragma unroll
        for (int i = 0; i < 4; i++) {
            int rr = r + i * 32;
            uint32_t so = swz((uint32_t)rr, (uint32_t)(c16 * 16));
            int mm = m0 + rr; if (mm > cnt - 1) mm = cnt - 1;
            cp16(ab + bufb + so, ahp + (size_t)mm * HDIM + k0 + c16 * 8);
        }
#pragma unroll
        for (int i = 0; i < 4; i++) {
            int rr = r + i * 32;
            uint32_t so = swz((uint32_t)rr, (uint32_t)(c16 * 16));
            cp16(ab + bufb + TILE_A + so, wf + (size_t)(n0 + rr) * HDIM + k0 + c16 * 8);
        }
        CP_COMMIT();
    };

    load_chunk(0, 0);
    load_chunk(1, STAGE_BYTES);
    for (int c = 0; c < NCH; c++) {
        if (c + 1 < NCH) CP_WAIT1(); else CP_WAIT0();
        __syncthreads();
        if (c + 2 < NCH) load_chunk(c + 2, (uint32_t)((c + 2) % NSTG) * STAGE_BYTES);
        compute_chunk(ab + (uint32_t)(c % NSTG) * STAGE_BYTES, wm, wn, lane, acc);
    }

    // Epilogue: (acc + b2) * wgt -> fp16 store into rank plane
    int g = lane >> 2, tig = lane & 3;
    const float* bias = b2 + (size_t)e * HDIM;
#pragma unroll
    for (int nt = 0; nt < 4; nt++) {
        int n = n0 + wn * 32 + nt * 8 + tig * 2;
        float bv0 = bias[n], bv1 = bias[n + 1];
#pragma unroll
        for (int mt = 0; mt < 4; mt++) {
#pragma unroll
            for (int half = 0; half < 2; half++) {
                int rl = wm * 64 + mt * 16 + g + half * 8;
                int m = m0 + rl;
                if (m < cnt) {
                    float w = s_wgt[rl];
                    float v0 = w * (acc[mt][nt][half * 2 + 0] + bv0);
                    float v1 = w * (acc[mt][nt][half * 2 + 1] + bv1);
                    __half2 hv = __floats2half2_rn(v0, v1);
                    __half* dst = g_outr[s_rnk[rl]] + (size_t)s_tok[rl] * HDIM + n;
                    *(uint32_t*)dst = *(uint32_t*)&hv;
                }
            }
        }
    }
}

// ---------------------------------------------------------------------------
// Combine: out = fp32(plane0) + fp32(plane1)   (fp16 planes -> fp32 out)
// ---------------------------------------------------------------------------
__global__ void combine_kernel(float4* __restrict__ out, long n4) {
    long i = (long)blockIdx.x * blockDim.x + threadIdx.x;
    long st = (long)gridDim.x * blockDim.x;
    const uint2* r0 = (const uint2*)g_outr[0];   // 4 halfs per uint2
    const uint2* r1 = (const uint2*)g_outr[1];
    for (; i < n4; i += st) {
        uint2 a = r0[i], b = r1[i];
        __half2 a0 = *(__half2*)&a.x, a1 = *(__half2*)&a.y;
        __half2 b0 = *(__half2*)&b.x, b1 = *(__half2*)&b.y;
        float2 fa0 = __half22float2(a0), fa1 = __half22float2(a1);
        float2 fb0 = __half22float2(b0), fb1 = __half22float2(b1);
        out[i] = make_float4(fa0.x + fb0.x, fa0.y + fb0.y,
                             fa1.x + fb1.x, fa1.y + fb1.y);
    }
}

// ---------------------------------------------------------------------------
extern "C" void kernel_launch(void* const* d_in, const int* in_sizes, int n_in,
                              void* d_out, int out_size) {
    const float* x  = (const float*)d_in[0];
    const float* gw = (const float*)d_in[1];
    const float* w1 = (const float*)d_in[2];
    const float* b1 = (const float*)d_in[3];
    const float* w2 = (const float*)d_in[4];
    const float* b2 = (const float*)d_in[5];
    float* out = (float*)d_out;

    cudaFuncSetAttribute(moe_gemm1, cudaFuncAttributeMaxDynamicSharedMemorySize, SMEM_TOTAL);
    cudaFuncSetAttribute(moe_gemm2, cudaFuncAttributeMaxDynamicSharedMemorySize, SMEM_TOTAL);

    reset_kernel<<<1, 32>>>();
    prep_x<<<NTOK / 8, 256>>>(x, gw);
    transpose_w<<<dim3(64, 64, 8), dim3(32, 8)>>>(w1, w2);

    moe_gemm1<<<dim3(HDIM / BN, NTOK / BM, NEXP), NTHREADS, SMEM_TOTAL>>>(b1);
    moe_gemm2<<<dim3(HDIM / BN, NTOK / BM, NEXP), NTHREADS, SMEM_TOTAL>>>(b2);
    combine_kernel<<<2048, 256>>>((float4*)out, (long)out_size / 4);
}